// round 16
// baseline (speedup 1.0000x reference)
#include <cuda_runtime.h>
#include <cuda_fp16.h>
#include <math.h>

#define BATCH 4096
#define AGENTS 32
#define NROWS (BATCH*AGENTS)      // 131072
#define NACT 16

// ---------------- scratch (device globals; no allocation) ----------------
__device__ __half g_obs_h[(size_t)NROWS*128];
__device__ __half g_Wemb_h[384*128];
__device__ float  g_bemb[384];
__device__ __half g_Wqkv_h[768*64];            // [net][192][64]
__device__ __half g_Wo_h[4*64*64];             // [net][64][64]
__device__ __half g_W1_h[256*384];
__device__ __half g_W2_h[256*256];
__device__ __half g_WaV_h[24*256];             // rows 0..15 Wa, 16 Wv, 17..23 zero
__device__ __half g_emb_h[(size_t)NROWS*384];  // [local(256) | intra(64) | inter->pooled(64)]
__device__ __half g_mha_h[(size_t)NROWS*256];  // post-Wo fp16
__device__ __half g_h1_h[(size_t)NROWS*256];
__device__ __half g_h2_h[(size_t)NROWS*256];

__device__ __forceinline__ float softplusf(float x) {
    return x > 20.0f ? x : log1pf(__expf(x));
}
__device__ __forceinline__ unsigned pk(float a, float b) {
    __half2 t = __floats2half2_rn(a, b);
    return *(unsigned*)&t;
}
__device__ __forceinline__ void mma_f16(float* c, const unsigned* a, unsigned b0, unsigned b1) {
    asm volatile("mma.sync.aligned.m16n8k16.row.col.f32.f16.f16.f32 "
                 "{%0,%1,%2,%3},{%4,%5,%6,%7},{%8,%9},{%0,%1,%2,%3};"
                 : "+f"(c[0]), "+f"(c[1]), "+f"(c[2]), "+f"(c[3])
                 : "r"(a[0]), "r"(a[1]), "r"(a[2]), "r"(a[3]), "r"(b0), "r"(b1));
}
__device__ __forceinline__ void cp16(unsigned s, const void* g) {
    asm volatile("cp.async.ca.shared.global [%0], [%1], 16;\n" :: "r"(s), "l"(g));
}
__device__ __forceinline__ void ldsm4(unsigned* r, const __half* p) {
    unsigned a = (unsigned)__cvta_generic_to_shared(p);
    asm volatile("ldmatrix.sync.aligned.m8n8.x4.shared.b16 {%0,%1,%2,%3}, [%4];"
                 : "=r"(r[0]), "=r"(r[1]), "=r"(r[2]), "=r"(r[3]) : "r"(a));
}
__device__ __forceinline__ void ldsm2(unsigned* r, const __half* p) {
    unsigned a = (unsigned)__cvta_generic_to_shared(p);
    asm volatile("ldmatrix.sync.aligned.m8n8.x2.shared.b16 {%0,%1}, [%2];"
                 : "=r"(r[0]), "=r"(r[1]) : "r"(a));
}
// A-fragment (16x16 tile): lane -> row (lane&15), col (lane>>4)*8
#define LDSM_A(frag, base, str, lane) \
    ldsm4(frag, (base) + ((lane) & 15) * (str) + (((lane) >> 4) << 3))
// B-pair (two n8 tiles): lane -> row (lane>>4)*8 + (lane&7), col ((lane>>3)&1)*8
#define LDSM_B2(frag, base, str, lane) \
    ldsm4(frag, (base) + ((((lane) >> 4) << 3) + ((lane) & 7)) * (str) + ((((lane) >> 3) & 1) << 3))
// B-single (one n8 tile): lane -> row (lane&7), col ((lane>>3)&1)*8
#define LDSM_B1(frag, base, str, lane) \
    ldsm2(frag, (base) + ((lane) & 7) * (str) + ((((lane) >> 3) & 1) << 3))

// ---------------- merged: obs -> fp16 + pack all weights -> fp16 ----------------
__global__ void prep_kernel(const float* __restrict__ obs,
                            const float* __restrict__ Wl, const float* __restrict__ bl,
                            const float* __restrict__ Wi, const float* __restrict__ bi,
                            const float* __restrict__ Wt, const float* __restrict__ bt,
                            const float* __restrict__ Wqkv, const float* __restrict__ Wo,
                            const float* __restrict__ W1, const float* __restrict__ W2,
                            const float* __restrict__ Wa, const float* __restrict__ Wv) {
    int idx = blockIdx.x * blockDim.x + threadIdx.x;
    {
        size_t i = (size_t)idx * 4;
        float4 v = *(const float4*)(obs + i);
        __half2* o = (__half2*)(g_obs_h + i);
        o[0] = __floats2half2_rn(v.x, v.y);
        o[1] = __floats2half2_rn(v.z, v.w);
    }
    if (idx < 384*128) {
        int row = idx >> 7, col = idx & 127;
        float v;
        if (row < 256)      v = Wl[row*128 + col];
        else if (row < 320) v = Wt[(row-256)*128 + col];
        else                v = Wi[(row-320)*128 + col];
        g_Wemb_h[idx] = __float2half_rn(v);
    }
    if (idx < 768*64)   g_Wqkv_h[idx] = __float2half_rn(Wqkv[idx]);
    if (idx < 4*64*64)  g_Wo_h[idx]   = __float2half_rn(Wo[idx]);
    if (idx < 256*384)  g_W1_h[idx]   = __float2half_rn(W1[idx]);
    if (idx < 256*256)  g_W2_h[idx]   = __float2half_rn(W2[idx]);
    if (idx < 24*256) {
        int row = idx >> 8, col = idx & 255;
        float v = (row < 16) ? Wa[row*256 + col] : (row == 16 ? Wv[col] : 0.0f);
        g_WaV_h[idx] = __float2half_rn(v);
    }
    if (idx < 384)
        g_bemb[idx] = (idx < 256) ? bl[idx] : (idx < 320 ? bt[idx-256] : bi[idx-320]);
}

// ---------------- FP16 tensor-core GEMM: BM=128, BN=64, 32x32 warp tiles ----------------
// 4 CTAs/SM target. Warps 4(m) x 2(n). Bitwise-identical accumulation to r15.
#define HSTR 40
template<int EPI, int OUTH>
__global__ __launch_bounds__(256, 4) void gemm_h(
    const __half* __restrict__ X, int ldx,
    const __half* __restrict__ W, const float* __restrict__ bias,
    void* __restrict__ Yv, int ldy, int K)
{
    extern __shared__ __half hsm[];
    __half* Xs = hsm;                        // [2][128*HSTR]
    __half* Ws = hsm + 2*128*HSTR;           // [2][64*HSTR]

    const int tid = threadIdx.x;
    const int m0 = blockIdx.x * 128, n0 = blockIdx.y * 64;
    const int warp = tid >> 5, lane = tid & 31;
    const int wm = (warp & 3) * 32, wn = (warp >> 2) * 32;
    const int l4 = lane >> 2, l2 = lane & 3;

    // g2s: threads 0-127 -> X row tid; threads 128-191 -> W row tid-128
    const int grow = (tid < 128) ? tid : (tid - 128);
    const bool gact = (tid < 192);
    const __half* grsrc = (tid < 128) ? (X + (size_t)(m0 + grow) * ldx)
                                      : (W + (size_t)(n0 + grow) * K);
    unsigned gdst0 = (unsigned)__cvta_generic_to_shared(
        ((tid < 128) ? Xs : Ws) + grow*HSTR);

    float acc[2][4][4];
#pragma unroll
    for (int a = 0; a < 2; a++)
#pragma unroll
        for (int b = 0; b < 4; b++)
#pragma unroll
            for (int c = 0; c < 4; c++) acc[a][b][c] = 0.0f;

    const int nstage = K >> 5;

    if (gact) {
#pragma unroll
        for (int q = 0; q < 4; q++)
            cp16(gdst0 + q*16, grsrc + q*8);
    }
    asm volatile("cp.async.commit_group;\n");

    for (int s = 0; s < nstage; s++) {
        asm volatile("cp.async.wait_group 0;\n");
        __syncthreads();

        if (s + 1 < nstage) {
            int k0 = (s + 1) << 5;
            unsigned gd = gdst0 + ((s+1)&1) * ((tid < 128) ? 128 : 64)*HSTR*2;
            if (gact) {
#pragma unroll
                for (int q = 0; q < 4; q++)
                    cp16(gd + q*16, grsrc + k0 + q*8);
            }
            asm volatile("cp.async.commit_group;\n");
        }

        const __half* Xb = Xs + (s & 1) * 128*HSTR;
        const __half* Wb = Ws + (s & 1) * 64*HSTR;
#pragma unroll
        for (int kb = 0; kb < 32; kb += 16) {
            unsigned afr[2][4], bfr[2][4];
#pragma unroll
            for (int mf = 0; mf < 2; mf++)
                LDSM_A(afr[mf], Xb + (wm + mf*16)*HSTR + kb, HSTR, lane);
            LDSM_B2(bfr[0], Wb + wn*HSTR + kb, HSTR, lane);
            LDSM_B2(bfr[1], Wb + (wn + 16)*HSTR + kb, HSTR, lane);
#pragma unroll
            for (int nf = 0; nf < 4; nf++) {
                unsigned b0 = bfr[nf >> 1][(nf & 1)*2];
                unsigned b1 = bfr[nf >> 1][(nf & 1)*2 + 1];
#pragma unroll
                for (int mf = 0; mf < 2; mf++)
                    mma_f16(acc[mf][nf], afr[mf], b0, b1);
            }
        }
    }

#pragma unroll
    for (int nf = 0; nf < 4; nf++) {
        int col = n0 + wn + nf*8 + l2*2;
        float bb0 = bias[col], bb1 = bias[col + 1];
#pragma unroll
        for (int mf = 0; mf < 2; mf++) {
            int row = m0 + wm + mf*16 + l4;
            float v0 = acc[mf][nf][0] + bb0, v1 = acc[mf][nf][1] + bb1;
            float v2 = acc[mf][nf][2] + bb0, v3 = acc[mf][nf][3] + bb1;
            if (EPI == 1) { v0 = tanhf(v0); v1 = tanhf(v1); v2 = tanhf(v2); v3 = tanhf(v3); }
            if (OUTH) {
                __half* Y = (__half*)Yv;
                *(__half2*)(Y + (size_t)row * ldy + col)       = __floats2half2_rn(v0, v1);
                *(__half2*)(Y + (size_t)(row + 8) * ldy + col) = __floats2half2_rn(v2, v3);
            } else {
                float* Y = (float*)Yv;
                float2 o01; o01.x = v0; o01.y = v1;
                float2 o23; o23.x = v2; o23.y = v3;
                *(float2*)(Y + (size_t)row * ldy + col) = o01;
                *(float2*)(Y + (size_t)(row + 8) * ldy + col) = o23;
            }
        }
    }
}
#define GEMMH_SMEM ((2*128 + 2*64)*HSTR*2)   // 30720 bytes

// ---------------- fused qkv + MMA-attention + Wo (r15, unchanged) ----------------
#define QKSTR 136
#define VTSTR 72
#define FSTR  72
#define SM_QK 0
#define SM_VT (64*QKSTR*2)                 // 17408
#define SM_XS (SM_VT + 64*VTSTR*2)         // 26624
#define SM_WS (SM_XS + 64*FSTR*2)          // 35840
#define SM_WO (SM_WS + 192*FSTR*2)         // 63488
#define FQ_SMEM (SM_WO + 64*FSTR*2)        // 72704

__global__ __launch_bounds__(256, 3) void qkv_attn_wo_kernel(
    const float* __restrict__ bqkv, const float* __restrict__ bo)
{
    extern __shared__ char sm[];
    __half* QKs = (__half*)(sm + SM_QK);    // [64][136]
    __half* Vt  = (__half*)(sm + SM_VT);    // [64][72]
    __half* Xs  = (__half*)(sm + SM_XS);    // [64][72]
    __half* Sa  = Xs;
    __half* Ws  = (__half*)(sm + SM_WS);    // [192][72]
    __half* Wo  = (__half*)(sm + SM_WO);    // [64][72]

    const int tid = threadIdx.x, warp = tid >> 5, lane = tid & 31;
    const int net = blockIdx.y;
    const int m0 = blockIdx.x * 64;
    const int l4 = lane >> 2, l2 = lane & 3;

    const int xoff = 256 + ((net >= 2) ? 64 : 0);
    {
        int xrow = tid >> 2, seg = tid & 3;
        const __half* src = g_emb_h + (size_t)(m0 + xrow) * 384 + xoff + seg*16;
        unsigned dst = (unsigned)__cvta_generic_to_shared(Xs + xrow*FSTR + seg*16);
        cp16(dst, src); cp16(dst + 16, src + 8);
        if (tid < 192) {
            const __half* ws = g_Wqkv_h + ((size_t)net*192 + tid) * 64;
            unsigned wd = (unsigned)__cvta_generic_to_shared(Ws + tid*FSTR);
#pragma unroll
            for (int q = 0; q < 8; q++) cp16(wd + q*16, ws + q*8);
        } else {
            int row = tid - 192;
            const __half* os = g_Wo_h + (size_t)net*4096 + row*64;
            unsigned od = (unsigned)__cvta_generic_to_shared(Wo + row*FSTR);
#pragma unroll
            for (int q = 0; q < 8; q++) cp16(od + q*16, os + q*8);
        }
    }
    asm volatile("cp.async.commit_group;\n");
    asm volatile("cp.async.wait_group 0;\n");
    __syncthreads();

    // ---- Phase A: qkv mma ----
    {
        const int wn = warp * 24;
        float acc[4][3][4];
#pragma unroll
        for (int a = 0; a < 4; a++)
#pragma unroll
            for (int b = 0; b < 3; b++)
#pragma unroll
                for (int c = 0; c < 4; c++) acc[a][b][c] = 0.0f;

#pragma unroll
        for (int kb = 0; kb < 64; kb += 16) {
            unsigned afr[4][4], bfr01[4], bfr2[2];
#pragma unroll
            for (int mf = 0; mf < 4; mf++)
                LDSM_A(afr[mf], Xs + (mf*16)*FSTR + kb, FSTR, lane);
            LDSM_B2(bfr01, Ws + wn*FSTR + kb, FSTR, lane);
            LDSM_B1(bfr2,  Ws + (wn + 16)*FSTR + kb, FSTR, lane);
#pragma unroll
            for (int nf = 0; nf < 3; nf++) {
                unsigned b0 = (nf < 2) ? bfr01[nf*2]     : bfr2[0];
                unsigned b1 = (nf < 2) ? bfr01[nf*2 + 1] : bfr2[1];
#pragma unroll
                for (int mf = 0; mf < 4; mf++)
                    mma_f16(acc[mf][nf], afr[mf], b0, b1);
            }
        }
#pragma unroll
        for (int nf = 0; nf < 3; nf++) {
            int col = wn + nf*8 + l2*2;
            float bb0 = bqkv[net*192 + col], bb1 = bqkv[net*192 + col + 1];
#pragma unroll
            for (int mf = 0; mf < 4; mf++) {
                int row = mf*16 + l4;
                float v0 = acc[mf][nf][0] + bb0, v1 = acc[mf][nf][1] + bb1;
                float v2 = acc[mf][nf][2] + bb0, v3 = acc[mf][nf][3] + bb1;
                if (col < 128) {
                    *(__half2*)(QKs + row*QKSTR + col)       = __floats2half2_rn(v0, v1);
                    *(__half2*)(QKs + (row + 8)*QKSTR + col) = __floats2half2_rn(v2, v3);
                } else {
                    int vc = col - 128;
                    Vt[vc*VTSTR + row]           = __float2half_rn(v0);
                    Vt[(vc + 1)*VTSTR + row]     = __float2half_rn(v1);
                    Vt[vc*VTSTR + row + 8]       = __float2half_rn(v2);
                    Vt[(vc + 1)*VTSTR + row + 8] = __float2half_rn(v3);
                }
            }
        }
    }
    __syncthreads();

    // ---- Phase B: MMA attention ----
    {
        const int g = warp >> 2, h = warp & 3;

        unsigned qa[2][4];
#pragma unroll
        for (int mf = 0; mf < 2; mf++)
            LDSM_A(qa[mf], QKs + (g*32 + mf*16)*QKSTR + h*16, QKSTR, lane);

        float sacc[2][4][4];
#pragma unroll
        for (int a = 0; a < 2; a++)
#pragma unroll
            for (int b = 0; b < 4; b++)
#pragma unroll
                for (int c = 0; c < 4; c++) sacc[a][b][c] = 0.0f;
        {
            unsigned kb01[4], kb23[4];
            LDSM_B2(kb01, QKs + (g*32)*QKSTR + 64 + h*16, QKSTR, lane);
            LDSM_B2(kb23, QKs + (g*32 + 16)*QKSTR + 64 + h*16, QKSTR, lane);
#pragma unroll
            for (int nf = 0; nf < 4; nf++) {
                unsigned b0 = (nf < 2) ? kb01[nf*2]     : kb23[(nf-2)*2];
                unsigned b1 = (nf < 2) ? kb01[nf*2 + 1] : kb23[(nf-2)*2 + 1];
#pragma unroll
                for (int mf = 0; mf < 2; mf++)
                    mma_f16(sacc[mf][nf], qa[mf], b0, b1);
            }
        }

        float rs[2][2];
        unsigned pa[2][2][4];
#pragma unroll
        for (int mf = 0; mf < 2; mf++) {
            float m0x = -1e30f, m1x = -1e30f;
#pragma unroll
            for (int nf = 0; nf < 4; nf++) {
                m0x = fmaxf(m0x, fmaxf(sacc[mf][nf][0], sacc[mf][nf][1]));
                m1x = fmaxf(m1x, fmaxf(sacc[mf][nf][2], sacc[mf][nf][3]));
            }
            m0x = fmaxf(m0x, __shfl_xor_sync(0xffffffffu, m0x, 1));
            m0x = fmaxf(m0x, __shfl_xor_sync(0xffffffffu, m0x, 2));
            m1x = fmaxf(m1x, __shfl_xor_sync(0xffffffffu, m1x, 1));
            m1x = fmaxf(m1x, __shfl_xor_sync(0xffffffffu, m1x, 2));

            float p[4][4];
            float s0 = 0.0f, s1 = 0.0f;
#pragma unroll
            for (int nf = 0; nf < 4; nf++) {
                p[nf][0] = __expf(0.25f * (sacc[mf][nf][0] - m0x));
                p[nf][1] = __expf(0.25f * (sacc[mf][nf][1] - m0x));
                p[nf][2] = __expf(0.25f * (sacc[mf][nf][2] - m1x));
                p[nf][3] = __expf(0.25f * (sacc[mf][nf][3] - m1x));
                s0 += p[nf][0] + p[nf][1];
                s1 += p[nf][2] + p[nf][3];
            }
            s0 += __shfl_xor_sync(0xffffffffu, s0, 1);
            s0 += __shfl_xor_sync(0xffffffffu, s0, 2);
            s1 += __shfl_xor_sync(0xffffffffu, s1, 1);
            s1 += __shfl_xor_sync(0xffffffffu, s1, 2);
            rs[mf][0] = 1.0f / s0;
            rs[mf][1] = 1.0f / s1;

            pa[mf][0][0] = pk(p[0][0], p[0][1]);
            pa[mf][0][1] = pk(p[0][2], p[0][3]);
            pa[mf][0][2] = pk(p[1][0], p[1][1]);
            pa[mf][0][3] = pk(p[1][2], p[1][3]);
            pa[mf][1][0] = pk(p[2][0], p[2][1]);
            pa[mf][1][1] = pk(p[2][2], p[2][3]);
            pa[mf][1][2] = pk(p[3][0], p[3][1]);
            pa[mf][1][3] = pk(p[3][2], p[3][3]);
        }

        float oacc[2][2][4];
#pragma unroll
        for (int a = 0; a < 2; a++)
#pragma unroll
            for (int b = 0; b < 2; b++)
#pragma unroll
                for (int c = 0; c < 4; c++) oacc[a][b][c] = 0.0f;
#pragma unroll
        for (int ks = 0; ks < 2; ks++) {
            unsigned vb[4];
            LDSM_B2(vb, Vt + (h*16)*VTSTR + g*32 + ks*16, VTSTR, lane);
#pragma unroll
            for (int nf = 0; nf < 2; nf++) {
                unsigned b0 = vb[nf*2], b1 = vb[nf*2 + 1];
#pragma unroll
                for (int mf = 0; mf < 2; mf++)
                    mma_f16(oacc[mf][nf], pa[mf][ks], b0, b1);
            }
        }

        __syncthreads();

#pragma unroll
        for (int nf = 0; nf < 2; nf++) {
            int col = h*16 + nf*8 + 2*l2;
#pragma unroll
            for (int mf = 0; mf < 2; mf++) {
                int row = g*32 + mf*16 + l4;
                *(__half2*)(Sa + row*FSTR + col) =
                    __floats2half2_rn(oacc[mf][nf][0]*rs[mf][0], oacc[mf][nf][1]*rs[mf][0]);
                *(__half2*)(Sa + (row + 8)*FSTR + col) =
                    __floats2half2_rn(oacc[mf][nf][2]*rs[mf][1], oacc[mf][nf][3]*rs[mf][1]);
            }
        }
    }
    __syncthreads();

    // ---- Phase C: Wo mma ----
    {
        const int wn = warp * 8;
        float acc[4][4];
#pragma unroll
        for (int a = 0; a < 4; a++)
#pragma unroll
            for (int c = 0; c < 4; c++) acc[a][c] = 0.0f;

#pragma unroll
        for (int kb = 0; kb < 64; kb += 16) {
            unsigned afr[4][4], bfr[2];
#pragma unroll
            for (int mf = 0; mf < 4; mf++)
                LDSM_A(afr[mf], Sa + (mf*16)*FSTR + kb, FSTR, lane);
            LDSM_B1(bfr, Wo + wn*FSTR + kb, FSTR, lane);
#pragma unroll
            for (int mf = 0; mf < 4; mf++)
                mma_f16(acc[mf], afr[mf], bfr[0], bfr[1]);
        }
        int col = wn + l2*2;
        float bb0 = bo[net*64 + col], bb1 = bo[net*64 + col + 1];
#pragma unroll
        for (int mf = 0; mf < 4; mf++) {
            int row = mf*16 + l4;
            *(__half2*)(g_mha_h + (size_t)(m0 + row) * 256 + net*64 + col) =
                __floats2half2_rn(acc[mf][0] + bb0, acc[mf][1] + bb1);
            *(__half2*)(g_mha_h + (size_t)(m0 + row + 8) * 256 + net*64 + col) =
                __floats2half2_rn(acc[mf][2] + bb0, acc[mf][3] + bb1);
        }
    }
}

// ---------------- reparameterise + softmax pooling: per batch ----------------
__global__ __launch_bounds__(256) void reparam_pool_kernel(
    const float* __restrict__ eps_intra, const float* __restrict__ eps_inter,
    const float* __restrict__ att_w, const float* __restrict__ att_b)
{
    __shared__ float sinter[32][65];
    __shared__ float ssc[32];
    const int b = blockIdx.x, tid = threadIdx.x;

#pragma unroll
    for (int i = 0; i < 8; i++) {
        int idx = tid + i*256;
        int r = idx >> 6, c = idx & 63;
        const __half* mh = g_mha_h + (size_t)(b*32 + r) * 256;
        float intra = __half2float(mh[c])
                    + softplusf(__half2float(mh[64 + c]) - 5.0f) * eps_intra[(size_t)(b*32 + r)*64 + c];
        g_emb_h[(size_t)(b*32 + r)*384 + 256 + c] = __float2half_rn(intra);
        float inter = __half2float(mh[128 + c])
                    + softplusf(__half2float(mh[192 + c]) - 5.0f) * eps_inter[(size_t)(b*32 + r)*64 + c];
        sinter[r][c] = inter;
    }
    __syncthreads();

    const int warp = tid >> 5, lane = tid & 31;
#pragma unroll
    for (int rr = 0; rr < 4; rr++) {
        int r = warp*4 + rr;
        float part = sinter[r][lane] * att_w[lane] + sinter[r][lane+32] * att_w[lane+32];
#pragma unroll
        for (int m = 16; m > 0; m >>= 1) part += __shfl_xor_sync(0xffffffffu, part, m);
        if (lane == 0) ssc[r] = part + att_b[0];
    }
    __syncthreads();

    if (warp == 0) {
        float l = ssc[lane];
        float mx = l;
#pragma unroll
        for (int m = 16; m > 0; m >>= 1) mx = fmaxf(mx, __shfl_xor_sync(0xffffffffu, mx, m));
        float e = __expf(l - mx);
        float sm = e;
#pragma unroll
        for (int m = 16; m > 0; m >>= 1) sm += __shfl_xor_sync(0xffffffffu, sm, m);
        ssc[lane] = e / sm;
    }
    __syncthreads();

    if (tid < 64) {
        float pooled = 0.0f;
#pragma unroll
        for (int r = 0; r < 32; r++) pooled += ssc[r] * sinter[r][tid];
        __half ph = __float2half_rn(pooled);
#pragma unroll
        for (int r = 0; r < 32; r++)
            g_emb_h[(size_t)(b*32 + r)*384 + 320 + tid] = ph;
    }
}

// ---------------- tensor-core action/value head (r15, unchanged) ----------------
#define HD_STR 264
#define HD_H2  (128*HD_STR)
#define HD_W   (24*HD_STR)
#define HD_SMEM ((HD_H2 + HD_W)*2)   // 80256 bytes

__global__ __launch_bounds__(256, 2) void head_mma_kernel(
    const float* __restrict__ ba, const float* __restrict__ bv,
    float* __restrict__ out)
{
    extern __shared__ __half hs[];
    __half* H  = hs;             // [128][264]
    __half* Wv = hs + HD_H2;     // [24][264]

    const int tid = threadIdx.x, warp = tid >> 5, lane = tid & 31;
    const int l4 = lane >> 2, l2 = lane & 3;
    const int r0 = blockIdx.x * 128;

    {
        int row = tid >> 1, hb = (tid & 1) * 128;
        const __half* src = g_h2_h + (size_t)(r0 + row) * 256 + hb;
        unsigned dst = (unsigned)__cvta_generic_to_shared(H + row*HD_STR + hb);
#pragma unroll
        for (int q = 0; q < 16; q++) cp16(dst + q*16, src + q*8);
    }
    for (int idx = tid; idx < 768; idx += 256) {
        int row = idx >> 5, seg = idx & 31;
        unsigned dst = (unsigned)__cvta_generic_to_shared(Wv + row*HD_STR + seg*8);
        cp16(dst, g_WaV_h + row*256 + seg*8);
    }
    asm volatile("cp.async.commit_group;\n");
    asm volatile("cp.async.wait_group 0;\n");
    __syncthreads();

    float acc[3][4];
#pragma unroll
    for (int b = 0; b < 3; b++)
#pragma unroll
        for (int c = 0; c < 4; c++) acc[b][c] = 0.0f;

#pragma unroll 4
    for (int kb = 0; kb < 256; kb += 16) {
        unsigned afr[4], bfr01[4], bfr2[2];
        LDSM_A(afr, H + (warp*16)*HD_STR + kb, HD_STR, lane);
        LDSM_B2(bfr01, Wv + kb, HD_STR, lane);
        LDSM_B1(bfr2,  Wv + 16*HD_STR + kb, HD_STR, lane);
        mma_f16(acc[0], afr, bfr01[0], bfr01[1]);
        mma_f16(acc[1], afr, bfr01[2], bfr01[3]);
        mma_f16(acc[2], afr, bfr2[0],  bfr2[1]);
    }

    float ba0 = ba[2*l2],     ba1 = ba[2*l2 + 1];
    float ba2 = ba[8 + 2*l2], ba3 = ba[8 + 2*l2 + 1];

    int row0 = r0 + warp*16 + l4;
#pragma unroll
    for (int rr = 0; rr < 2; rr++) {
        float a0 = acc[0][rr*2]     + ba0;
        float a1 = acc[0][rr*2 + 1] + ba1;
        float a2 = acc[1][rr*2]     + ba2;
        float a3 = acc[1][rr*2 + 1] + ba3;

        float mx = fmaxf(fmaxf(a0, a1), fmaxf(a2, a3));
        mx = fmaxf(mx, __shfl_xor_sync(0xffffffffu, mx, 1));
        mx = fmaxf(mx, __shfl_xor_sync(0xffffffffu, mx, 2));
        float e0 = __expf(a0 - mx), e1 = __expf(a1 - mx);
        float e2 = __expf(a2 - mx), e3 = __expf(a3 - mx);
        float sm = e0 + e1 + e2 + e3;
        sm += __shfl_xor_sync(0xffffffffu, sm, 1);
        sm += __shfl_xor_sync(0xffffffffu, sm, 2);
        float lse = mx + logf(sm);

        int row = row0 + rr*8;
        float2 o01; o01.x = a0 - lse; o01.y = a1 - lse;
        float2 o23; o23.x = a2 - lse; o23.y = a3 - lse;
        *(float2*)(out + (size_t)row * 16 + 2*l2)     = o01;
        *(float2*)(out + (size_t)row * 16 + 8 + 2*l2) = o23;

        if (l2 == 0)
            out[(size_t)NROWS * 16 + row] = acc[2][rr*2] + bv[0];
    }
}

// ---------------- launch ----------------
extern "C" void kernel_launch(void* const* d_in, const int* in_sizes, int n_in,
                              void* d_out, int out_size) {
    const float* obs       = (const float*)d_in[0];
    const float* eps_intra = (const float*)d_in[1];
    const float* eps_inter = (const float*)d_in[2];
    const float* W_local   = (const float*)d_in[3];
    const float* b_local   = (const float*)d_in[4];
    const float* W_inter   = (const float*)d_in[5];
    const float* b_inter   = (const float*)d_in[6];
    const float* W_intra   = (const float*)d_in[7];
    const float* b_intra   = (const float*)d_in[8];
    const float* Wqkv      = (const float*)d_in[9];
    const float* bqkv      = (const float*)d_in[10];
    const float* Wo        = (const float*)d_in[11];
    const float* bo        = (const float*)d_in[12];
    const float* att_w     = (const float*)d_in[13];
    const float* att_b     = (const float*)d_in[14];
    const float* W1        = (const float*)d_in[15];
    const float* b1        = (const float*)d_in[16];
    const float* W2        = (const float*)d_in[17];
    const float* b2        = (const float*)d_in[18];
    const float* Wa        = (const float*)d_in[19];
    const float* ba        = (const float*)d_in[20];
    const float* Wv        = (const float*)d_in[21];
    const float* bv        = (const float*)d_in[22];
    float* out = (float*)d_out;

    __half *p_obs_h, *p_Wemb_h, *p_W1_h, *p_W2_h, *p_emb_h, *p_h1_h, *p_h2_h;
    float  *p_bemb;
    cudaGetSymbolAddress((void**)&p_obs_h,  g_obs_h);
    cudaGetSymbolAddress((void**)&p_Wemb_h, g_Wemb_h);
    cudaGetSymbolAddress((void**)&p_W1_h,   g_W1_h);
    cudaGetSymbolAddress((void**)&p_W2_h,   g_W2_h);
    cudaGetSymbolAddress((void**)&p_emb_h,  g_emb_h);
    cudaGetSymbolAddress((void**)&p_h1_h,   g_h1_h);
    cudaGetSymbolAddress((void**)&p_h2_h,   g_h2_h);
    cudaGetSymbolAddress((void**)&p_bemb,   g_bemb);

    cudaFuncSetAttribute(qkv_attn_wo_kernel, cudaFuncAttributeMaxDynamicSharedMemorySize, FQ_SMEM);
    cudaFuncSetAttribute(head_mma_kernel,    cudaFuncAttributeMaxDynamicSharedMemorySize, HD_SMEM);

    const int MB = NROWS / 128;   // 1024

    // 1) convert obs + pack weights
    prep_kernel<<<NROWS*128/1024, 256>>>(obs, W_local, b_local, W_inter, b_inter,
                                         W_intra, b_intra, Wqkv, Wo, W1, W2, Wa, Wv);

    // 2) embeddings (BN=64 -> y=6)
    gemm_h<1,1><<<dim3(MB, 6), 256, GEMMH_SMEM>>>(p_obs_h, 128, p_Wemb_h, p_bemb,
                                                  p_emb_h, 384, 128);

    // 3) fused qkv + MMA attention + Wo
    qkv_attn_wo_kernel<<<dim3(NROWS/64, 4), 256, FQ_SMEM>>>(bqkv, bo);

    // 4) reparameterise + softmax pooling
    reparam_pool_kernel<<<BATCH, 256>>>(eps_intra, eps_inter, att_w, att_b);

    // 5) MLP (BN=64 -> y=4)
    gemm_h<1,1><<<dim3(MB, 4), 256, GEMMH_SMEM>>>(p_emb_h, 384, p_W1_h, b1,
                                                  p_h1_h, 256, 384);
    gemm_h<1,1><<<dim3(MB, 4), 256, GEMMH_SMEM>>>(p_h1_h, 256, p_W2_h, b2,
                                                  p_h2_h, 256, 256);

    // 6) tensor-core action/value head
    head_mma_kernel<<<NROWS/128, 256, HD_SMEM>>>(ba, bv, out);
}

// round 17
// speedup vs baseline: 1.1653x; 1.1653x over previous
#include <cuda_runtime.h>
#include <cuda_fp16.h>
#include <math.h>

#define BATCH 4096
#define AGENTS 32
#define NROWS (BATCH*AGENTS)      // 131072
#define NACT 16

// ---------------- scratch (device globals; no allocation) ----------------
__device__ __half g_obs_h[(size_t)NROWS*128];
__device__ __half g_Wemb_h[384*128];
__device__ float  g_bemb[384];
__device__ __half g_Wqkv_h[768*64];            // [net][192][64]
__device__ __half g_Wo_h[4*64*64];             // [net][64][64]
__device__ __half g_W1_h[256*384];
__device__ __half g_W2_h[256*256];
__device__ __half g_WaV_h[24*256];             // rows 0..15 Wa, 16 Wv, 17..23 zero
__device__ __half g_emb_h[(size_t)NROWS*384];  // [local(256) | intra(64) | inter->pooled(64)]
__device__ __half g_mha_h[(size_t)NROWS*256];  // post-Wo fp16
__device__ __half g_h1_h[(size_t)NROWS*256];
__device__ __half g_h2_h[(size_t)NROWS*256];

__device__ __forceinline__ float softplusf(float x) {
    return x > 20.0f ? x : log1pf(__expf(x));
}
__device__ __forceinline__ unsigned pk(float a, float b) {
    __half2 t = __floats2half2_rn(a, b);
    return *(unsigned*)&t;
}
__device__ __forceinline__ void mma_f16(float* c, const unsigned* a, unsigned b0, unsigned b1) {
    asm volatile("mma.sync.aligned.m16n8k16.row.col.f32.f16.f16.f32 "
                 "{%0,%1,%2,%3},{%4,%5,%6,%7},{%8,%9},{%0,%1,%2,%3};"
                 : "+f"(c[0]), "+f"(c[1]), "+f"(c[2]), "+f"(c[3])
                 : "r"(a[0]), "r"(a[1]), "r"(a[2]), "r"(a[3]), "r"(b0), "r"(b1));
}
__device__ __forceinline__ void cp16(unsigned s, const void* g) {
    asm volatile("cp.async.ca.shared.global [%0], [%1], 16;\n" :: "r"(s), "l"(g));
}
__device__ __forceinline__ void ldsm4(unsigned* r, const __half* p) {
    unsigned a = (unsigned)__cvta_generic_to_shared(p);
    asm volatile("ldmatrix.sync.aligned.m8n8.x4.shared.b16 {%0,%1,%2,%3}, [%4];"
                 : "=r"(r[0]), "=r"(r[1]), "=r"(r[2]), "=r"(r[3]) : "r"(a));
}
__device__ __forceinline__ void ldsm2(unsigned* r, const __half* p) {
    unsigned a = (unsigned)__cvta_generic_to_shared(p);
    asm volatile("ldmatrix.sync.aligned.m8n8.x2.shared.b16 {%0,%1}, [%2];"
                 : "=r"(r[0]), "=r"(r[1]) : "r"(a));
}
// A-fragment (16x16 tile): lane -> row (lane&15), col (lane>>4)*8
#define LDSM_A(frag, base, str, lane) \
    ldsm4(frag, (base) + ((lane) & 15) * (str) + (((lane) >> 4) << 3))
// B-pair (two n8 tiles): lane -> row (lane>>4)*8 + (lane&7), col ((lane>>3)&1)*8
#define LDSM_B2(frag, base, str, lane) \
    ldsm4(frag, (base) + ((((lane) >> 4) << 3) + ((lane) & 7)) * (str) + ((((lane) >> 3) & 1) << 3))
// B-single (one n8 tile): lane -> row (lane&7), col ((lane>>3)&1)*8
#define LDSM_B1(frag, base, str, lane) \
    ldsm2(frag, (base) + ((lane) & 7) * (str) + ((((lane) >> 3) & 1) << 3))

// ---------------- merged: obs -> fp16 + pack all weights -> fp16 ----------------
__global__ void prep_kernel(const float* __restrict__ obs,
                            const float* __restrict__ Wl, const float* __restrict__ bl,
                            const float* __restrict__ Wi, const float* __restrict__ bi,
                            const float* __restrict__ Wt, const float* __restrict__ bt,
                            const float* __restrict__ Wqkv, const float* __restrict__ Wo,
                            const float* __restrict__ W1, const float* __restrict__ W2,
                            const float* __restrict__ Wa, const float* __restrict__ Wv) {
    int idx = blockIdx.x * blockDim.x + threadIdx.x;
    {
        size_t i = (size_t)idx * 4;
        float4 v = *(const float4*)(obs + i);
        __half2* o = (__half2*)(g_obs_h + i);
        o[0] = __floats2half2_rn(v.x, v.y);
        o[1] = __floats2half2_rn(v.z, v.w);
    }
    if (idx < 384*128) {
        int row = idx >> 7, col = idx & 127;
        float v;
        if (row < 256)      v = Wl[row*128 + col];
        else if (row < 320) v = Wt[(row-256)*128 + col];
        else                v = Wi[(row-320)*128 + col];
        g_Wemb_h[idx] = __float2half_rn(v);
    }
    if (idx < 768*64)   g_Wqkv_h[idx] = __float2half_rn(Wqkv[idx]);
    if (idx < 4*64*64)  g_Wo_h[idx]   = __float2half_rn(Wo[idx]);
    if (idx < 256*384)  g_W1_h[idx]   = __float2half_rn(W1[idx]);
    if (idx < 256*256)  g_W2_h[idx]   = __float2half_rn(W2[idx]);
    if (idx < 24*256) {
        int row = idx >> 8, col = idx & 255;
        float v = (row < 16) ? Wa[row*256 + col] : (row == 16 ? Wv[col] : 0.0f);
        g_WaV_h[idx] = __float2half_rn(v);
    }
    if (idx < 384)
        g_bemb[idx] = (idx < 256) ? bl[idx] : (idx < 320 ? bt[idx-256] : bi[idx-320]);
}

// ---------------- FP16 tensor-core GEMM (r15 validated: BM=128, BN=128) ----------------
#define HSTR 40
template<int EPI, int OUTH>
__global__ __launch_bounds__(256, 2) void gemm_h(
    const __half* __restrict__ X, int ldx,
    const __half* __restrict__ W, const float* __restrict__ bias,
    void* __restrict__ Yv, int ldy, int K)
{
    extern __shared__ __half hsm[];
    __half* Xs = hsm;                        // [2][128*HSTR]
    __half* Ws = hsm + 2*128*HSTR;           // [2][128*HSTR]

    const int tid = threadIdx.x;
    const int m0 = blockIdx.x * 128, n0 = blockIdx.y * 128;
    const int warp = tid >> 5, lane = tid & 31;
    const int wm = (warp & 1) * 64, wn = (warp >> 1) * 32;
    const int l4 = lane >> 2, l2 = lane & 3;

    const int grow = tid & 127, gmat = tid >> 7;
    const __half* grsrc = gmat ? (W + (size_t)(n0 + grow) * K)
                               : (X + (size_t)(m0 + grow) * ldx);
    unsigned gdst0 = (unsigned)__cvta_generic_to_shared(
        (gmat ? Ws : Xs) + grow*HSTR);

    float acc[4][4][4];
#pragma unroll
    for (int a = 0; a < 4; a++)
#pragma unroll
        for (int b = 0; b < 4; b++)
#pragma unroll
            for (int c = 0; c < 4; c++) acc[a][b][c] = 0.0f;

    const int nstage = K >> 5;

#pragma unroll
    for (int q = 0; q < 4; q++)
        cp16(gdst0 + q*16, grsrc + q*8);
    asm volatile("cp.async.commit_group;\n");

    for (int s = 0; s < nstage; s++) {
        asm volatile("cp.async.wait_group 0;\n");
        __syncthreads();

        if (s + 1 < nstage) {
            int k0 = (s + 1) << 5;
            unsigned gd = gdst0 + ((s+1)&1) * 128*HSTR*2;
#pragma unroll
            for (int q = 0; q < 4; q++)
                cp16(gd + q*16, grsrc + k0 + q*8);
            asm volatile("cp.async.commit_group;\n");
        }

        const __half* Xb = Xs + (s & 1) * 128*HSTR;
        const __half* Wb = Ws + (s & 1) * 128*HSTR;
#pragma unroll
        for (int kb = 0; kb < 32; kb += 16) {
            unsigned afr[4][4], bfr[2][4];
#pragma unroll
            for (int mf = 0; mf < 4; mf++)
                LDSM_A(afr[mf], Xb + (wm + mf*16)*HSTR + kb, HSTR, lane);
            LDSM_B2(bfr[0], Wb + wn*HSTR + kb, HSTR, lane);
            LDSM_B2(bfr[1], Wb + (wn + 16)*HSTR + kb, HSTR, lane);
#pragma unroll
            for (int nf = 0; nf < 4; nf++) {
                unsigned b0 = bfr[nf >> 1][(nf & 1)*2];
                unsigned b1 = bfr[nf >> 1][(nf & 1)*2 + 1];
#pragma unroll
                for (int mf = 0; mf < 4; mf++)
                    mma_f16(acc[mf][nf], afr[mf], b0, b1);
            }
        }
    }

#pragma unroll
    for (int nf = 0; nf < 4; nf++) {
        int col = n0 + wn + nf*8 + l2*2;
        float bb0 = bias[col], bb1 = bias[col + 1];
#pragma unroll
        for (int mf = 0; mf < 4; mf++) {
            int row = m0 + wm + mf*16 + l4;
            float v0 = acc[mf][nf][0] + bb0, v1 = acc[mf][nf][1] + bb1;
            float v2 = acc[mf][nf][2] + bb0, v3 = acc[mf][nf][3] + bb1;
            if (EPI == 1) { v0 = tanhf(v0); v1 = tanhf(v1); v2 = tanhf(v2); v3 = tanhf(v3); }
            if (OUTH) {
                __half* Y = (__half*)Yv;
                *(__half2*)(Y + (size_t)row * ldy + col)       = __floats2half2_rn(v0, v1);
                *(__half2*)(Y + (size_t)(row + 8) * ldy + col) = __floats2half2_rn(v2, v3);
            } else {
                float* Y = (float*)Yv;
                float2 o01; o01.x = v0; o01.y = v1;
                float2 o23; o23.x = v2; o23.y = v3;
                *(float2*)(Y + (size_t)row * ldy + col) = o01;
                *(float2*)(Y + (size_t)(row + 8) * ldy + col) = o23;
            }
        }
    }
}
#define GEMMH_SMEM (4*128*HSTR*2)   // 40960 bytes

// ---------------- fused qkv + MMA-attention + Wo (r15, unchanged) ----------------
#define QKSTR 136
#define VTSTR 72
#define FSTR  72
#define SM_QK 0
#define SM_VT (64*QKSTR*2)                 // 17408
#define SM_XS (SM_VT + 64*VTSTR*2)         // 26624
#define SM_WS (SM_XS + 64*FSTR*2)          // 35840
#define SM_WO (SM_WS + 192*FSTR*2)         // 63488
#define FQ_SMEM (SM_WO + 64*FSTR*2)        // 72704

__global__ __launch_bounds__(256, 3) void qkv_attn_wo_kernel(
    const float* __restrict__ bqkv, const float* __restrict__ bo)
{
    extern __shared__ char sm[];
    __half* QKs = (__half*)(sm + SM_QK);    // [64][136]
    __half* Vt  = (__half*)(sm + SM_VT);    // [64][72]
    __half* Xs  = (__half*)(sm + SM_XS);    // [64][72]
    __half* Sa  = Xs;
    __half* Ws  = (__half*)(sm + SM_WS);    // [192][72]
    __half* Wo  = (__half*)(sm + SM_WO);    // [64][72]

    const int tid = threadIdx.x, warp = tid >> 5, lane = tid & 31;
    const int net = blockIdx.y;
    const int m0 = blockIdx.x * 64;
    const int l4 = lane >> 2, l2 = lane & 3;

    const int xoff = 256 + ((net >= 2) ? 64 : 0);
    {
        int xrow = tid >> 2, seg = tid & 3;
        const __half* src = g_emb_h + (size_t)(m0 + xrow) * 384 + xoff + seg*16;
        unsigned dst = (unsigned)__cvta_generic_to_shared(Xs + xrow*FSTR + seg*16);
        cp16(dst, src); cp16(dst + 16, src + 8);
        if (tid < 192) {
            const __half* ws = g_Wqkv_h + ((size_t)net*192 + tid) * 64;
            unsigned wd = (unsigned)__cvta_generic_to_shared(Ws + tid*FSTR);
#pragma unroll
            for (int q = 0; q < 8; q++) cp16(wd + q*16, ws + q*8);
        } else {
            int row = tid - 192;
            const __half* os = g_Wo_h + (size_t)net*4096 + row*64;
            unsigned od = (unsigned)__cvta_generic_to_shared(Wo + row*FSTR);
#pragma unroll
            for (int q = 0; q < 8; q++) cp16(od + q*16, os + q*8);
        }
    }
    asm volatile("cp.async.commit_group;\n");
    asm volatile("cp.async.wait_group 0;\n");
    __syncthreads();

    // ---- Phase A: qkv mma ----
    {
        const int wn = warp * 24;
        float acc[4][3][4];
#pragma unroll
        for (int a = 0; a < 4; a++)
#pragma unroll
            for (int b = 0; b < 3; b++)
#pragma unroll
                for (int c = 0; c < 4; c++) acc[a][b][c] = 0.0f;

#pragma unroll
        for (int kb = 0; kb < 64; kb += 16) {
            unsigned afr[4][4], bfr01[4], bfr2[2];
#pragma unroll
            for (int mf = 0; mf < 4; mf++)
                LDSM_A(afr[mf], Xs + (mf*16)*FSTR + kb, FSTR, lane);
            LDSM_B2(bfr01, Ws + wn*FSTR + kb, FSTR, lane);
            LDSM_B1(bfr2,  Ws + (wn + 16)*FSTR + kb, FSTR, lane);
#pragma unroll
            for (int nf = 0; nf < 3; nf++) {
                unsigned b0 = (nf < 2) ? bfr01[nf*2]     : bfr2[0];
                unsigned b1 = (nf < 2) ? bfr01[nf*2 + 1] : bfr2[1];
#pragma unroll
                for (int mf = 0; mf < 4; mf++)
                    mma_f16(acc[mf][nf], afr[mf], b0, b1);
            }
        }
#pragma unroll
        for (int nf = 0; nf < 3; nf++) {
            int col = wn + nf*8 + l2*2;
            float bb0 = bqkv[net*192 + col], bb1 = bqkv[net*192 + col + 1];
#pragma unroll
            for (int mf = 0; mf < 4; mf++) {
                int row = mf*16 + l4;
                float v0 = acc[mf][nf][0] + bb0, v1 = acc[mf][nf][1] + bb1;
                float v2 = acc[mf][nf][2] + bb0, v3 = acc[mf][nf][3] + bb1;
                if (col < 128) {
                    *(__half2*)(QKs + row*QKSTR + col)       = __floats2half2_rn(v0, v1);
                    *(__half2*)(QKs + (row + 8)*QKSTR + col) = __floats2half2_rn(v2, v3);
                } else {
                    int vc = col - 128;
                    Vt[vc*VTSTR + row]           = __float2half_rn(v0);
                    Vt[(vc + 1)*VTSTR + row]     = __float2half_rn(v1);
                    Vt[vc*VTSTR + row + 8]       = __float2half_rn(v2);
                    Vt[(vc + 1)*VTSTR + row + 8] = __float2half_rn(v3);
                }
            }
        }
    }
    __syncthreads();

    // ---- Phase B: MMA attention ----
    {
        const int g = warp >> 2, h = warp & 3;

        unsigned qa[2][4];
#pragma unroll
        for (int mf = 0; mf < 2; mf++)
            LDSM_A(qa[mf], QKs + (g*32 + mf*16)*QKSTR + h*16, QKSTR, lane);

        float sacc[2][4][4];
#pragma unroll
        for (int a = 0; a < 2; a++)
#pragma unroll
            for (int b = 0; b < 4; b++)
#pragma unroll
                for (int c = 0; c < 4; c++) sacc[a][b][c] = 0.0f;
        {
            unsigned kb01[4], kb23[4];
            LDSM_B2(kb01, QKs + (g*32)*QKSTR + 64 + h*16, QKSTR, lane);
            LDSM_B2(kb23, QKs + (g*32 + 16)*QKSTR + 64 + h*16, QKSTR, lane);
#pragma unroll
            for (int nf = 0; nf < 4; nf++) {
                unsigned b0 = (nf < 2) ? kb01[nf*2]     : kb23[(nf-2)*2];
                unsigned b1 = (nf < 2) ? kb01[nf*2 + 1] : kb23[(nf-2)*2 + 1];
#pragma unroll
                for (int mf = 0; mf < 2; mf++)
                    mma_f16(sacc[mf][nf], qa[mf], b0, b1);
            }
        }

        float rs[2][2];
        unsigned pa[2][2][4];
#pragma unroll
        for (int mf = 0; mf < 2; mf++) {
            float m0x = -1e30f, m1x = -1e30f;
#pragma unroll
            for (int nf = 0; nf < 4; nf++) {
                m0x = fmaxf(m0x, fmaxf(sacc[mf][nf][0], sacc[mf][nf][1]));
                m1x = fmaxf(m1x, fmaxf(sacc[mf][nf][2], sacc[mf][nf][3]));
            }
            m0x = fmaxf(m0x, __shfl_xor_sync(0xffffffffu, m0x, 1));
            m0x = fmaxf(m0x, __shfl_xor_sync(0xffffffffu, m0x, 2));
            m1x = fmaxf(m1x, __shfl_xor_sync(0xffffffffu, m1x, 1));
            m1x = fmaxf(m1x, __shfl_xor_sync(0xffffffffu, m1x, 2));

            float p[4][4];
            float s0 = 0.0f, s1 = 0.0f;
#pragma unroll
            for (int nf = 0; nf < 4; nf++) {
                p[nf][0] = __expf(0.25f * (sacc[mf][nf][0] - m0x));
                p[nf][1] = __expf(0.25f * (sacc[mf][nf][1] - m0x));
                p[nf][2] = __expf(0.25f * (sacc[mf][nf][2] - m1x));
                p[nf][3] = __expf(0.25f * (sacc[mf][nf][3] - m1x));
                s0 += p[nf][0] + p[nf][1];
                s1 += p[nf][2] + p[nf][3];
            }
            s0 += __shfl_xor_sync(0xffffffffu, s0, 1);
            s0 += __shfl_xor_sync(0xffffffffu, s0, 2);
            s1 += __shfl_xor_sync(0xffffffffu, s1, 1);
            s1 += __shfl_xor_sync(0xffffffffu, s1, 2);
            rs[mf][0] = 1.0f / s0;
            rs[mf][1] = 1.0f / s1;

            pa[mf][0][0] = pk(p[0][0], p[0][1]);
            pa[mf][0][1] = pk(p[0][2], p[0][3]);
            pa[mf][0][2] = pk(p[1][0], p[1][1]);
            pa[mf][0][3] = pk(p[1][2], p[1][3]);
            pa[mf][1][0] = pk(p[2][0], p[2][1]);
            pa[mf][1][1] = pk(p[2][2], p[2][3]);
            pa[mf][1][2] = pk(p[3][0], p[3][1]);
            pa[mf][1][3] = pk(p[3][2], p[3][3]);
        }

        float oacc[2][2][4];
#pragma unroll
        for (int a = 0; a < 2; a++)
#pragma unroll
            for (int b = 0; b < 2; b++)
#pragma unroll
                for (int c = 0; c < 4; c++) oacc[a][b][c] = 0.0f;
#pragma unroll
        for (int ks = 0; ks < 2; ks++) {
            unsigned vb[4];
            LDSM_B2(vb, Vt + (h*16)*VTSTR + g*32 + ks*16, VTSTR, lane);
#pragma unroll
            for (int nf = 0; nf < 2; nf++) {
                unsigned b0 = vb[nf*2], b1 = vb[nf*2 + 1];
#pragma unroll
                for (int mf = 0; mf < 2; mf++)
                    mma_f16(oacc[mf][nf], pa[mf][ks], b0, b1);
            }
        }

        __syncthreads();

#pragma unroll
        for (int nf = 0; nf < 2; nf++) {
            int col = h*16 + nf*8 + 2*l2;
#pragma unroll
            for (int mf = 0; mf < 2; mf++) {
                int row = g*32 + mf*16 + l4;
                *(__half2*)(Sa + row*FSTR + col) =
                    __floats2half2_rn(oacc[mf][nf][0]*rs[mf][0], oacc[mf][nf][1]*rs[mf][0]);
                *(__half2*)(Sa + (row + 8)*FSTR + col) =
                    __floats2half2_rn(oacc[mf][nf][2]*rs[mf][1], oacc[mf][nf][3]*rs[mf][1]);
            }
        }
    }
    __syncthreads();

    // ---- Phase C: Wo mma ----
    {
        const int wn = warp * 8;
        float acc[4][4];
#pragma unroll
        for (int a = 0; a < 4; a++)
#pragma unroll
            for (int c = 0; c < 4; c++) acc[a][c] = 0.0f;

#pragma unroll
        for (int kb = 0; kb < 64; kb += 16) {
            unsigned afr[4][4], bfr[2];
#pragma unroll
            for (int mf = 0; mf < 4; mf++)
                LDSM_A(afr[mf], Sa + (mf*16)*FSTR + kb, FSTR, lane);
            LDSM_B1(bfr, Wo + wn*FSTR + kb, FSTR, lane);
#pragma unroll
            for (int mf = 0; mf < 4; mf++)
                mma_f16(acc[mf], afr[mf], bfr[0], bfr[1]);
        }
        int col = wn + l2*2;
        float bb0 = bo[net*64 + col], bb1 = bo[net*64 + col + 1];
#pragma unroll
        for (int mf = 0; mf < 4; mf++) {
            int row = mf*16 + l4;
            *(__half2*)(g_mha_h + (size_t)(m0 + row) * 256 + net*64 + col) =
                __floats2half2_rn(acc[mf][0] + bb0, acc[mf][1] + bb1);
            *(__half2*)(g_mha_h + (size_t)(m0 + row + 8) * 256 + net*64 + col) =
                __floats2half2_rn(acc[mf][2] + bb0, acc[mf][3] + bb1);
        }
    }
}

// ---------------- reparameterise + softmax pooling (vectorized loads) ----------------
__global__ __launch_bounds__(256) void reparam_pool_kernel(
    const float* __restrict__ eps_intra, const float* __restrict__ eps_inter,
    const float* __restrict__ att_w, const float* __restrict__ att_b)
{
    __shared__ float sinter[32][65];
    __shared__ float ssc[32];
    const int b = blockIdx.x, tid = threadIdx.x;

#pragma unroll
    for (int i = 0; i < 4; i++) {
        int idx = tid + i*256;                 // 0..1023 = 32 rows x 32 col-pairs
        int r = idx >> 5, c = (idx & 31) << 1;
        const __half* mh = g_mha_h + (size_t)(b*32 + r) * 256;
        __half2 m0 = *(const __half2*)(mh + c);
        __half2 m1 = *(const __half2*)(mh + 64 + c);
        __half2 m2 = *(const __half2*)(mh + 128 + c);
        __half2 m3 = *(const __half2*)(mh + 192 + c);
        float2 ei = *(const float2*)(eps_intra + (size_t)(b*32 + r)*64 + c);
        float2 et = *(const float2*)(eps_inter + (size_t)(b*32 + r)*64 + c);

        float i0 = __half2float(m0.x) + softplusf(__half2float(m1.x) - 5.0f) * ei.x;
        float i1 = __half2float(m0.y) + softplusf(__half2float(m1.y) - 5.0f) * ei.y;
        *(__half2*)(g_emb_h + (size_t)(b*32 + r)*384 + 256 + c) = __floats2half2_rn(i0, i1);

        float t0 = __half2float(m2.x) + softplusf(__half2float(m3.x) - 5.0f) * et.x;
        float t1 = __half2float(m2.y) + softplusf(__half2float(m3.y) - 5.0f) * et.y;
        sinter[r][c] = t0;
        sinter[r][c + 1] = t1;
    }
    __syncthreads();

    const int warp = tid >> 5, lane = tid & 31;
#pragma unroll
    for (int rr = 0; rr < 4; rr++) {
        int r = warp*4 + rr;
        float part = sinter[r][lane] * att_w[lane] + sinter[r][lane+32] * att_w[lane+32];
#pragma unroll
        for (int m = 16; m > 0; m >>= 1) part += __shfl_xor_sync(0xffffffffu, part, m);
        if (lane == 0) ssc[r] = part + att_b[0];
    }
    __syncthreads();

    if (warp == 0) {
        float l = ssc[lane];
        float mx = l;
#pragma unroll
        for (int m = 16; m > 0; m >>= 1) mx = fmaxf(mx, __shfl_xor_sync(0xffffffffu, mx, m));
        float e = __expf(l - mx);
        float sm = e;
#pragma unroll
        for (int m = 16; m > 0; m >>= 1) sm += __shfl_xor_sync(0xffffffffu, sm, m);
        ssc[lane] = e / sm;
    }
    __syncthreads();

    if (tid < 64) {
        float pooled = 0.0f;
#pragma unroll
        for (int r = 0; r < 32; r++) pooled += ssc[r] * sinter[r][tid];
        __half ph = __float2half_rn(pooled);
#pragma unroll
        for (int r = 0; r < 32; r++)
            g_emb_h[(size_t)(b*32 + r)*384 + 320 + tid] = ph;
    }
}

// ---------------- tensor-core action/value head (r15, unchanged) ----------------
#define HD_STR 264
#define HD_H2  (128*HD_STR)
#define HD_W   (24*HD_STR)
#define HD_SMEM ((HD_H2 + HD_W)*2)   // 80256 bytes

__global__ __launch_bounds__(256, 2) void head_mma_kernel(
    const float* __restrict__ ba, const float* __restrict__ bv,
    float* __restrict__ out)
{
    extern __shared__ __half hs[];
    __half* H  = hs;             // [128][264]
    __half* Wv = hs + HD_H2;     // [24][264]

    const int tid = threadIdx.x, warp = tid >> 5, lane = tid & 31;
    const int l4 = lane >> 2, l2 = lane & 3;
    const int r0 = blockIdx.x * 128;

    {
        int row = tid >> 1, hb = (tid & 1) * 128;
        const __half* src = g_h2_h + (size_t)(r0 + row) * 256 + hb;
        unsigned dst = (unsigned)__cvta_generic_to_shared(H + row*HD_STR + hb);
#pragma unroll
        for (int q = 0; q < 16; q++) cp16(dst + q*16, src + q*8);
    }
    for (int idx = tid; idx < 768; idx += 256) {
        int row = idx >> 5, seg = idx & 31;
        unsigned dst = (unsigned)__cvta_generic_to_shared(Wv + row*HD_STR + seg*8);
        cp16(dst, g_WaV_h + row*256 + seg*8);
    }
    asm volatile("cp.async.commit_group;\n");
    asm volatile("cp.async.wait_group 0;\n");
    __syncthreads();

    float acc[3][4];
#pragma unroll
    for (int b = 0; b < 3; b++)
#pragma unroll
        for (int c = 0; c < 4; c++) acc[b][c] = 0.0f;

#pragma unroll 4
    for (int kb = 0; kb < 256; kb += 16) {
        unsigned afr[4], bfr01[4], bfr2[2];
        LDSM_A(afr, H + (warp*16)*HD_STR + kb, HD_STR, lane);
        LDSM_B2(bfr01, Wv + kb, HD_STR, lane);
        LDSM_B1(bfr2,  Wv + 16*HD_STR + kb, HD_STR, lane);
        mma_f16(acc[0], afr, bfr01[0], bfr01[1]);
        mma_f16(acc[1], afr, bfr01[2], bfr01[3]);
        mma_f16(acc[2], afr, bfr2[0],  bfr2[1]);
    }

    float ba0 = ba[2*l2],     ba1 = ba[2*l2 + 1];
    float ba2 = ba[8 + 2*l2], ba3 = ba[8 + 2*l2 + 1];

    int row0 = r0 + warp*16 + l4;
#pragma unroll
    for (int rr = 0; rr < 2; rr++) {
        float a0 = acc[0][rr*2]     + ba0;
        float a1 = acc[0][rr*2 + 1] + ba1;
        float a2 = acc[1][rr*2]     + ba2;
        float a3 = acc[1][rr*2 + 1] + ba3;

        float mx = fmaxf(fmaxf(a0, a1), fmaxf(a2, a3));
        mx = fmaxf(mx, __shfl_xor_sync(0xffffffffu, mx, 1));
        mx = fmaxf(mx, __shfl_xor_sync(0xffffffffu, mx, 2));
        float e0 = __expf(a0 - mx), e1 = __expf(a1 - mx);
        float e2 = __expf(a2 - mx), e3 = __expf(a3 - mx);
        float sm = e0 + e1 + e2 + e3;
        sm += __shfl_xor_sync(0xffffffffu, sm, 1);
        sm += __shfl_xor_sync(0xffffffffu, sm, 2);
        float lse = mx + logf(sm);

        int row = row0 + rr*8;
        float2 o01; o01.x = a0 - lse; o01.y = a1 - lse;
        float2 o23; o23.x = a2 - lse; o23.y = a3 - lse;
        *(float2*)(out + (size_t)row * 16 + 2*l2)     = o01;
        *(float2*)(out + (size_t)row * 16 + 8 + 2*l2) = o23;

        if (l2 == 0)
            out[(size_t)NROWS * 16 + row] = acc[2][rr*2] + bv[0];
    }
}

// ---------------- launch ----------------
extern "C" void kernel_launch(void* const* d_in, const int* in_sizes, int n_in,
                              void* d_out, int out_size) {
    const float* obs       = (const float*)d_in[0];
    const float* eps_intra = (const float*)d_in[1];
    const float* eps_inter = (const float*)d_in[2];
    const float* W_local   = (const float*)d_in[3];
    const float* b_local   = (const float*)d_in[4];
    const float* W_inter   = (const float*)d_in[5];
    const float* b_inter   = (const float*)d_in[6];
    const float* W_intra   = (const float*)d_in[7];
    const float* b_intra   = (const float*)d_in[8];
    const float* Wqkv      = (const float*)d_in[9];
    const float* bqkv      = (const float*)d_in[10];
    const float* Wo        = (const float*)d_in[11];
    const float* bo        = (const float*)d_in[12];
    const float* att_w     = (const float*)d_in[13];
    const float* att_b     = (const float*)d_in[14];
    const float* W1        = (const float*)d_in[15];
    const float* b1        = (const float*)d_in[16];
    const float* W2        = (const float*)d_in[17];
    const float* b2        = (const float*)d_in[18];
    const float* Wa        = (const float*)d_in[19];
    const float* ba        = (const float*)d_in[20];
    const float* Wv        = (const float*)d_in[21];
    const float* bv        = (const float*)d_in[22];
    float* out = (float*)d_out;

    __half *p_obs_h, *p_Wemb_h, *p_W1_h, *p_W2_h, *p_emb_h, *p_h1_h, *p_h2_h;
    float  *p_bemb;
    cudaGetSymbolAddress((void**)&p_obs_h,  g_obs_h);
    cudaGetSymbolAddress((void**)&p_Wemb_h, g_Wemb_h);
    cudaGetSymbolAddress((void**)&p_W1_h,   g_W1_h);
    cudaGetSymbolAddress((void**)&p_W2_h,   g_W2_h);
    cudaGetSymbolAddress((void**)&p_emb_h,  g_emb_h);
    cudaGetSymbolAddress((void**)&p_h1_h,   g_h1_h);
    cudaGetSymbolAddress((void**)&p_h2_h,   g_h2_h);
    cudaGetSymbolAddress((void**)&p_bemb,   g_bemb);

    cudaFuncSetAttribute(qkv_attn_wo_kernel, cudaFuncAttributeMaxDynamicSharedMemorySize, FQ_SMEM);
    cudaFuncSetAttribute(head_mma_kernel,    cudaFuncAttributeMaxDynamicSharedMemorySize, HD_SMEM);

    const int MB = NROWS / 128;   // 1024

    // 1) convert obs + pack weights
    prep_kernel<<<NROWS*128/1024, 256>>>(obs, W_local, b_local, W_inter, b_inter,
                                         W_intra, b_intra, Wqkv, Wo, W1, W2, Wa, Wv);

    // 2) embeddings (BN=128 -> y=3)
    gemm_h<1,1><<<dim3(MB, 3), 256, GEMMH_SMEM>>>(p_obs_h, 128, p_Wemb_h, p_bemb,
                                                  p_emb_h, 384, 128);

    // 3) fused qkv + MMA attention + Wo
    qkv_attn_wo_kernel<<<dim3(NROWS/64, 4), 256, FQ_SMEM>>>(bqkv, bo);

    // 4) reparameterise + softmax pooling
    reparam_pool_kernel<<<BATCH, 256>>>(eps_intra, eps_inter, att_w, att_b);

    // 5) MLP (BN=128 -> y=2)
    gemm_h<1,1><<<dim3(MB, 2), 256, GEMMH_SMEM>>>(p_emb_h, 384, p_W1_h, b1,
                                                  p_h1_h, 256, 384);
    gemm_h<1,1><<<dim3(MB, 2), 256, GEMMH_SMEM>>>(p_h1_h, 256, p_W2_h, b2,
                                                  p_h2_h, 256, 256);

    // 6) tensor-core action/value head
    head_mma_kernel<<<NROWS/128, 256, HD_SMEM>>>(ba, bv, out);
}